// round 16
// baseline (speedup 1.0000x reference)
#include <cuda_runtime.h>
#include <cstdint>
#include <math.h>

#define N_NODES   50000
#define N_EDGES   800000
#define HDIM      96
#define NUM_IN    11
#define PE_DIM    24
#define N_LAYERS  4
#define N_GRAPHS  256
#define NTILES    (N_EDGES / 128)

// ---------------- scratch (device globals; no allocations allowed) ----------
__device__ float g_h   [N_NODES * HDIM];
__device__ float g_A   [N_NODES * HDIM];
__device__ float g_B   [N_NODES * HDIM];
__device__ float g_aggr[N_NODES * HDIM];
__device__ float g_u   [N_NODES * HDIM];
__device__ float g_dist[N_EDGES];
__device__ int   g_send[N_EDGES];
__device__ int   g_rec [N_EDGES];
// sorted-by-rec copies
__device__ float g_sdist[N_EDGES];
__device__ int   g_ssend[N_EDGES];
__device__ int   g_srec [N_EDGES];
__device__ int   g_cnt  [N_NODES];
__device__ float g_pooled[N_GRAPHS * HDIM];
// fp32 transposed weights WT[n][k] (staging for packing)
__device__ float g_WT[248832];
// packed bf16-pair weights (hi, lo): per 96-block of K: 48 words, layout
// word[(j%4)*12 + j/4] = bf16x2(k=2j, k=2j+1)
__device__ uint32_t g_Wp  [124416];
__device__ uint32_t g_Wplo[124416];

__device__ __forceinline__ float silu_f(float v) {
    return v / (1.0f + __expf(-v));
}
__device__ __forceinline__ void red_add_v4(float* p, float4 v) {
    asm volatile("red.global.add.v4.f32 [%0], {%1,%2,%3,%4};"
                 :: "l"(p), "f"(v.x), "f"(v.y), "f"(v.z), "f"(v.w) : "memory");
}
__device__ __forceinline__ uint32_t pkbf2(float x, float y) {
    uint32_t r;
    asm("cvt.rn.bf16x2.f32 %0, %1, %2;" : "=r"(r) : "f"(y), "f"(x));
    return r;
}
__device__ __forceinline__ float2 upbf2(uint32_t w) {
    float2 f;
    f.x = __uint_as_float(w << 16);
    f.y = __uint_as_float(w & 0xffff0000u);
    return f;
}
__device__ __forceinline__ void bfsplit2(float x, float y, uint32_t& h, uint32_t& l) {
    h = pkbf2(x, y);
    float2 r = upbf2(h);
    l = pkbf2(x - r.x, y - r.y);
}
__device__ __forceinline__ void mma16(float* d, uint32_t a0, uint32_t a1,
                                      uint32_t a2, uint32_t a3,
                                      uint32_t b0, uint32_t b1) {
    asm volatile(
        "mma.sync.aligned.m16n8k16.row.col.f32.bf16.bf16.f32 "
        "{%0,%1,%2,%3}, {%4,%5,%6,%7}, {%8,%9}, {%0,%1,%2,%3};"
        : "+f"(d[0]), "+f"(d[1]), "+f"(d[2]), "+f"(d[3])
        : "r"(a0), "r"(a1), "r"(a2), "r"(a3), "r"(b0), "r"(b1));
}

// SMEM word offsets: rows of 48 uint32 (pair-permuted), conflict-free LDS.128
// NOTE: C staging (floats, stride 100, 12800 words) aliases A (12288 words) and
// spills 512 words past it — so B starts at 12800, NOT 12288 (persistent-loop
// safety: stage-C must never touch the resident weights).
#define AHI_W 0        // 128*48 = 6144
#define ALO_W 6144
#define BHI_W 12800    // 96*48 = 4608
#define BLO_W 17408
#define XTR_W 22016    // edge extras

// ---------------- edge preprocessing + histogram, dtype-robust --------------
__global__ void zero_cnt_kernel() {
    int i = blockIdx.x * 1024 + threadIdx.x;
    if (i < N_NODES) g_cnt[i] = 0;
}
__global__ void edge_prep(const int* __restrict__ eraw, const float* __restrict__ pos) {
    __shared__ int s_is64;
    if (threadIdx.x == 0) {
        s_is64 = ((eraw[2*N_EDGES-1] | eraw[2*N_EDGES-3] |
                   eraw[2*N_EDGES-5] | eraw[2*N_EDGES-7]) == 0) ? 1 : 0;
    }
    __syncthreads();
    int e = blockIdx.x * blockDim.x + threadIdx.x;
    if (e >= N_EDGES) return;
    int s, r;
    if (s_is64) {
        const long long* e64 = (const long long*)eraw;
        s = (int)e64[e]; r = (int)e64[N_EDGES + e];
    } else {
        s = eraw[e];     r = eraw[N_EDGES + e];
    }
    g_send[e] = s; g_rec[e] = r;
    float dx = pos[3*s+0] - pos[3*r+0];
    float dy = pos[3*s+1] - pos[3*r+1];
    float dz = pos[3*s+2] - pos[3*r+2];
    g_dist[e] = sqrtf(dx*dx + dy*dy + dz*dz);
    atomicAdd(&g_cnt[r], 1);
}
// 1-block exclusive prefix sum over g_cnt (becomes scatter cursor)
__global__ void __launch_bounds__(1024)
scan_kernel() {
    __shared__ int ssum[1024];
    int t = threadIdx.x;
    int beg = t * 49;
    int end = beg + 49; if (end > N_NODES) end = N_NODES;
    int s = 0;
    for (int i = beg; i < end; i++) s += g_cnt[i];
    ssum[t] = s;
    __syncthreads();
    for (int d = 1; d < 1024; d <<= 1) {
        int v = (t >= d) ? ssum[t - d] : 0;
        __syncthreads();
        ssum[t] += v;
        __syncthreads();
    }
    int off = (t > 0) ? ssum[t - 1] : 0;
    for (int i = beg; i < end; i++) {
        int c = g_cnt[i];
        g_cnt[i] = off;
        off += c;
    }
}
__global__ void scatter_kernel() {
    int e = blockIdx.x * blockDim.x + threadIdx.x;
    if (e >= N_EDGES) return;
    int r = g_rec[e];
    int pos = atomicAdd(&g_cnt[r], 1);
    g_ssend[pos] = g_send[e];
    g_srec [pos] = r;
    g_sdist[pos] = g_dist[e];
}

// ---------------- weight transpose (fp32 staging) ---------------------------
__global__ void __launch_bounds__(1024)
transpose_all(const float* __restrict__ mw1, const float* __restrict__ mw2,
              const float* __restrict__ uw1, const float* __restrict__ uw2,
              const float* __restrict__ ew2, const float* __restrict__ pw1,
              const float* __restrict__ pw2)
{
    __shared__ float t[32][33];
    int bid = blockIdx.x;
    const float* src; float* dst; int K; int tile;
    if (bid < 216) {
        int l = bid / 54, sub = bid % 54;
        float* WTl = g_WT + l * 55296;
        if (sub < 9)       { src = mw1 + (size_t)l*193*96;        dst = WTl;         K = 96;  tile = sub; }
        else if (sub < 18) { src = mw1 + (size_t)l*193*96 + 9216; dst = WTl + 9216;  K = 96;  tile = sub - 9; }
        else if (sub < 27) { src = mw2 + (size_t)l*9216;          dst = WTl + 18432; K = 96;  tile = sub - 18; }
        else if (sub < 45) { src = uw1 + (size_t)l*18432;         dst = WTl + 27648; K = 192; tile = sub - 27; }
        else               { src = uw2 + (size_t)l*9216;          dst = WTl + 46080; K = 96;  tile = sub - 45; }
    } else if (bid < 225) { src = ew2; dst = g_WT + 221184; K = 96; tile = bid - 216; }
    else if (bid < 234)   { src = pw1; dst = g_WT + 230400; K = 96; tile = bid - 225; }
    else                  { src = pw2; dst = g_WT + 239616; K = 96; tile = bid - 234; }
    int bx = tile % 3, by = tile / 3;
    int tx = threadIdx.x & 31, ty = threadIdx.x >> 5;
    t[ty][tx] = src[(by*32 + ty) * 96 + bx*32 + tx];
    __syncthreads();
    dst[(bx*32 + ty) * K + by*32 + tx] = t[tx][ty];
}

// pack fp32 WT into bf16-pair hi/lo in the SMEM-ready permuted layout
__global__ void __launch_bounds__(1024)
pack_weights() {
    int w = blockIdx.x * 1024 + threadIdx.x;
    if (w >= 124416) return;
    int b = w / 48, o = w - b * 48;
    int q = o % 12, tcp = o / 12;
    int j = 4 * q + tcp;
    int f = b * 96 + 2 * j;
    float x = g_WT[f], y = g_WT[f + 1];
    uint32_t h, l;
    bfsplit2(x, y, h, l);
    g_Wp[w] = h; g_Wplo[w] = l;
}

// ---- shared 3xBF16 mainloop: 8 warps (2m x 4n), warp tile 64 rows x 24 cols
__device__ __forceinline__ void mma3_loop(const uint32_t* apH, const uint32_t* apL,
                                          const uint32_t* bpH, const uint32_t* bpL,
                                          float acc[4][3][4])
{
    #pragma unroll
    for (int g = 0; g < 3; g++) {
        uint4 bh[3], bl[3];
        #pragma unroll
        for (int nf = 0; nf < 3; nf++) {
            bh[nf] = *(const uint4*)(bpH + nf * 384 + 4 * g);
            bl[nf] = *(const uint4*)(bpL + nf * 384 + 4 * g);
        }
        #pragma unroll
        for (int mf = 0; mf < 4; mf++) {
            uint4 xh = *(const uint4*)(apH + mf * 768 + 4 * g);
            uint4 yh = *(const uint4*)(apH + mf * 768 + 384 + 4 * g);
            uint4 xl = *(const uint4*)(apL + mf * 768 + 4 * g);
            uint4 yl = *(const uint4*)(apL + mf * 768 + 384 + 4 * g);
            #pragma unroll
            for (int nf = 0; nf < 3; nf++) {
                mma16(acc[mf][nf], xh.x, yh.x, xh.y, yh.y, bh[nf].x, bh[nf].y);
                mma16(acc[mf][nf], xh.x, yh.x, xh.y, yh.y, bl[nf].x, bl[nf].y);
                mma16(acc[mf][nf], xl.x, yl.x, xl.y, yl.y, bh[nf].x, bh[nf].y);
                mma16(acc[mf][nf], xh.z, yh.z, xh.w, yh.w, bh[nf].z, bh[nf].w);
                mma16(acc[mf][nf], xh.z, yh.z, xh.w, yh.w, bl[nf].z, bl[nf].w);
                mma16(acc[mf][nf], xl.z, yl.z, xl.w, yl.w, bh[nf].z, bh[nf].w);
            }
        }
    }
}

// store A pair (float4 covering k=4*k4..4*k4+3) as hi/lo packed words
__device__ __forceinline__ void store_apair(uint32_t* Ah, uint32_t* Al,
                                            int row, int k4, float4 v)
{
    uint32_t h0, l0, h1, l1;
    bfsplit2(v.x, v.y, h0, l0);
    bfsplit2(v.z, v.w, h1, l1);
    int j0 = 2 * k4, j1 = 2 * k4 + 1;
    int o0 = (j0 & 3) * 12 + (j0 >> 2);
    int o1 = (j1 & 3) * 12 + (j1 >> 2);
    Ah[row * 48 + o0] = h0; Ah[row * 48 + o1] = h1;
    Al[row * 48 + o0] = l0; Al[row * 48 + o1] = l1;
}

// ---------------- mma node MLP: out = act([in1|in2] @ W + b)[+res] ----------
// 256 thr = 8 warps (2 m x 4 n), CTA tile 128 rows x 96 cols, K in 96-chunks
__global__ void __launch_bounds__(256, 2)
mma_node(const float* __restrict__ in1, const float* __restrict__ in2,
         const uint32_t* __restrict__ Wp, const uint32_t* __restrict__ Wplo, int Kc,
         const float* __restrict__ bias, const float* __restrict__ res,
         float* __restrict__ out, int nrows, int do_silu)
{
    extern __shared__ uint32_t smw[];
    uint32_t* Ah = smw + AHI_W;
    uint32_t* Al = smw + ALO_W;
    uint32_t* Bh = smw + BHI_W;
    uint32_t* Bl = smw + BLO_W;
    float*    Cs = (float*)smw;

    const int tid = threadIdx.x;
    const int w   = tid >> 5, lane = tid & 31;
    const int wm  = w & 1, wn = w >> 1;
    const int tr  = lane >> 2, tc = lane & 3;
    const int base = blockIdx.x * 128;

    float acc[4][3][4];
    #pragma unroll
    for (int mf = 0; mf < 4; mf++)
        #pragma unroll
        for (int nf = 0; nf < 3; nf++)
            #pragma unroll
            for (int c = 0; c < 4; c++) acc[mf][nf][c] = 0.0f;

    for (int ch = 0; ch < Kc; ch++) {
        const float* src = (ch == 0) ? in1 : in2;
        #pragma unroll
        for (int it = 0; it < 12; it++) {
            int idx = it * 256 + tid;
            int row = idx / 24, k4 = idx - row * 24;
            int grow = base + row;
            float4 v = make_float4(0.f, 0.f, 0.f, 0.f);
            if (grow < nrows) v = *(const float4*)&src[(size_t)grow * 96 + k4 * 4];
            store_apair(Ah, Al, row, k4, v);
        }
        #pragma unroll
        for (int it = 0; it < 5; it++) {
            int idx = it * 256 + tid;
            if (idx < 1152) {
                int n = idx / 12, o4 = idx - n * 12;
                const uint4* sh = (const uint4*)(Wp   + ((size_t)n * Kc + ch) * 48) + o4;
                const uint4* sl = (const uint4*)(Wplo + ((size_t)n * Kc + ch) * 48) + o4;
                ((uint4*)(Bh + n * 48))[o4] = *sh;
                ((uint4*)(Bl + n * 48))[o4] = *sl;
            }
        }
        __syncthreads();

        const uint32_t* apH = Ah + (wm * 64 + tr) * 48 + tc * 12;
        const uint32_t* apL = Al + (wm * 64 + tr) * 48 + tc * 12;
        const uint32_t* bpH = Bh + (wn * 24 + tr) * 48 + tc * 12;
        const uint32_t* bpL = Bl + (wn * 24 + tr) * 48 + tc * 12;
        mma3_loop(apH, apL, bpH, bpL, acc);
        __syncthreads();
    }

    #pragma unroll
    for (int mf = 0; mf < 4; mf++) {
        int row = wm * 64 + mf * 16 + tr;
        int col = wn * 24 + 2 * tc;
        #pragma unroll
        for (int nf = 0; nf < 3; nf++) {
            Cs[row * 100 + col + nf*8]       = acc[mf][nf][0];
            Cs[row * 100 + col + nf*8 + 1]   = acc[mf][nf][1];
            Cs[(row+8) * 100 + col + nf*8]   = acc[mf][nf][2];
            Cs[(row+8) * 100 + col + nf*8+1] = acc[mf][nf][3];
        }
    }
    __syncthreads();

    #pragma unroll
    for (int it = 0; it < 12; it++) {
        int idx = it * 256 + tid;
        int row = idx / 24, j4 = idx - row * 24;
        int grow = base + row;
        if (grow >= nrows) continue;
        float4 v = *(const float4*)&Cs[row * 100 + j4 * 4];
        if (bias) {
            float4 b = *(const float4*)&bias[j4 * 4];
            v.x += b.x; v.y += b.y; v.z += b.z; v.w += b.w;
        }
        if (do_silu) {
            v.x = silu_f(v.x); v.y = silu_f(v.y);
            v.z = silu_f(v.z); v.w = silu_f(v.w);
        }
        if (res) {
            float4 rv = *(const float4*)&res[(size_t)grow * 96 + j4 * 4];
            v.x += rv.x; v.y += rv.y; v.z += rv.z; v.w += rv.w;
        }
        *(float4*)&out[(size_t)grow * 96 + j4 * 4] = v;
    }
}

// ---------------- PERSISTENT mma edge kernel --------------------------------
// 296 CTAs grid-stride over tiles; W2 resident in SMEM across all tiles.
// t = silu(A[s]+B[r]+d*wl+b1); m = silu(t@W2+b2);
// epilogue: warp-local segmented scan (sorted rec), tail lanes red.add
__global__ void __launch_bounds__(256, 2)
mma_edge(const uint32_t* __restrict__ Wp, const uint32_t* __restrict__ Wplo,
         const float* __restrict__ wl, const float* __restrict__ b1,
         const float* __restrict__ b2)
{
    extern __shared__ uint32_t smw[];
    uint32_t* Ah = smw + AHI_W;
    uint32_t* Al = smw + ALO_W;
    uint32_t* Bh = smw + BHI_W;
    uint32_t* Bl = smw + BLO_W;
    float*    Cs = (float*)smw;
    float* b1s = (float*)(smw + XTR_W);
    float* b2s = b1s + 96;
    float* wls = b2s + 96;
    float* de  = wls + 96;
    int*   se  = (int*)(de + 128);
    int*   re  = se + 128;

    const int tid = threadIdx.x;
    const int w   = tid >> 5, lane = tid & 31;
    const int wm  = w & 1, wn = w >> 1;
    const int tr  = lane >> 2, tc = lane & 3;

    // one-time: biases + resident weights
    if (tid < 96) { b1s[tid] = b1[tid]; b2s[tid] = b2[tid]; wls[tid] = wl[tid]; }
    #pragma unroll
    for (int it = 0; it < 5; it++) {
        int idx = it * 256 + tid;
        if (idx < 1152) {
            int n = idx / 12, o4 = idx - n * 12;
            ((uint4*)(Bh + n * 48))[o4] = ((const uint4*)(Wp   + (size_t)n * 48))[o4];
            ((uint4*)(Bl + n * 48))[o4] = ((const uint4*)(Wplo + (size_t)n * 48))[o4];
        }
    }

    for (int tile = blockIdx.x; tile < NTILES; tile += gridDim.x) {
        const int base = tile * 128;
        __syncthreads();   // prev epilogue (reads re/Cs) done before overwrite
        if (tid < 128) {
            int e = base + tid;
            se[tid] = g_ssend[e]; re[tid] = g_srec[e]; de[tid] = g_sdist[e];
        }
        __syncthreads();

        #pragma unroll
        for (int it = 0; it < 12; it++) {
            int idx = it * 256 + tid;
            int e = idx / 24, k4 = idx - e * 24;
            int kf = k4 * 4;
            int s = se[e], r = re[e];
            float dd = de[e];
            float4 a  = *(const float4*)&g_A[(size_t)s * 96 + kf];
            float4 b  = *(const float4*)&g_B[(size_t)r * 96 + kf];
            float4 w4 = *(const float4*)&wls[kf];
            float4 c4 = *(const float4*)&b1s[kf];
            float4 t;
            t.x = silu_f(a.x + b.x + dd * w4.x + c4.x);
            t.y = silu_f(a.y + b.y + dd * w4.y + c4.y);
            t.z = silu_f(a.z + b.z + dd * w4.z + c4.z);
            t.w = silu_f(a.w + b.w + dd * w4.w + c4.w);
            store_apair(Ah, Al, e, k4, t);
        }
        __syncthreads();

        float acc[4][3][4];
        #pragma unroll
        for (int mf = 0; mf < 4; mf++)
            #pragma unroll
            for (int nf = 0; nf < 3; nf++)
                #pragma unroll
                for (int c = 0; c < 4; c++) acc[mf][nf][c] = 0.0f;

        const uint32_t* apH = Ah + (wm * 64 + tr) * 48 + tc * 12;
        const uint32_t* apL = Al + (wm * 64 + tr) * 48 + tc * 12;
        const uint32_t* bpH = Bh + (wn * 24 + tr) * 48 + tc * 12;
        const uint32_t* bpL = Bl + (wn * 24 + tr) * 48 + tc * 12;
        mma3_loop(apH, apL, bpH, bpL, acc);
        __syncthreads();   // mainloop A-reads done before stage-C overwrites

        #pragma unroll
        for (int mf = 0; mf < 4; mf++) {
            int row = wm * 64 + mf * 16 + tr;
            int col = wn * 24 + 2 * tc;
            #pragma unroll
            for (int nf = 0; nf < 3; nf++) {
                Cs[row * 100 + col + nf*8]       = acc[mf][nf][0];
                Cs[row * 100 + col + nf*8 + 1]   = acc[mf][nf][1];
                Cs[(row+8) * 100 + col + nf*8]   = acc[mf][nf][2];
                Cs[(row+8) * 100 + col + nf*8+1] = acc[mf][nf][3];
            }
        }
        __syncthreads();

        // segmented-scan epilogue: 96 warp-tasks = (group 0..3) x (j4 0..23)
        for (int t = w; t < 96; t += 8) {
            int grp = t & 3, j4 = t >> 2;
            int row = grp * 32 + lane;
            int node = re[row];
            float4 b = *(const float4*)&b2s[j4 * 4];
            float4 v = *(const float4*)&Cs[row * 100 + j4 * 4];
            v.x = silu_f(v.x + b.x); v.y = silu_f(v.y + b.y);
            v.z = silu_f(v.z + b.z); v.w = silu_f(v.w + b.w);
            #pragma unroll
            for (int d = 1; d < 32; d <<= 1) {
                float ox = __shfl_up_sync(0xffffffffu, v.x, d);
                float oy = __shfl_up_sync(0xffffffffu, v.y, d);
                float oz = __shfl_up_sync(0xffffffffu, v.z, d);
                float ow = __shfl_up_sync(0xffffffffu, v.w, d);
                int   on = __shfl_up_sync(0xffffffffu, node, d);
                if (lane >= d && on == node) {
                    v.x += ox; v.y += oy; v.z += oz; v.w += ow;
                }
            }
            int nn = __shfl_down_sync(0xffffffffu, node, 1);
            bool tail = (lane == 31) || (nn != node);
            if (tail) red_add_v4(&g_aggr[(size_t)node * 96 + j4 * 4], v);
        }
    }
}

// ---------------- scalar node MLP (embed layer 1 only, K=11+24) -------------
__global__ void __launch_bounds__(384, 2)
node_mlp(const float* __restrict__ in1, int K1, const float* __restrict__ W1,
         const float* __restrict__ in2, int K2, const float* __restrict__ W2,
         const float* __restrict__ bias, float* __restrict__ out,
         int nrows, int do_silu)
{
    extern __shared__ float smf[];
    const int K1p = (K1 + 3) & ~3;
    const int K2p = (K2 + 3) & ~3;
    float* Ws1 = smf;
    float* Ws2 = smf + K1p * 96;
    float* sT  = Ws2 + K2p * 96;

    const int tid  = threadIdx.y * 24 + threadIdx.x;
    const int base = blockIdx.x * 64;
    const int f0   = threadIdx.x * 4;
    const int r0   = threadIdx.y * 4;

    for (int idx = tid; idx < K1p * 96; idx += 384) {
        int k = idx / 96;
        Ws1[idx] = (k < K1) ? W1[idx] : 0.0f;
    }
    if (in2) {
        for (int idx = tid; idx < K2p * 96; idx += 384) {
            int k = idx / 96;
            Ws2[idx] = (k < K2) ? W2[idx] : 0.0f;
        }
    }

    float acc[4][4];
    #pragma unroll
    for (int i = 0; i < 4; i++)
        #pragma unroll
        for (int c = 0; c < 4; c++) acc[i][c] = 0.0f;

    for (int idx = tid; idx < 64 * K1p; idx += 384) {
        int k = idx / 64, e = idx - (k * 64);
        int row = base + e;
        sT[k*64 + e] = (k < K1 && row < nrows) ? in1[(size_t)row * K1 + k] : 0.0f;
    }
    __syncthreads();
    for (int k = 0; k < K1p; k++) {
        float4 w = *(const float4*)&Ws1[k*96 + f0];
        #pragma unroll
        for (int i = 0; i < 4; i++) {
            float tv = sT[k*64 + r0 + i];
            acc[i][0] += tv * w.x; acc[i][1] += tv * w.y;
            acc[i][2] += tv * w.z; acc[i][3] += tv * w.w;
        }
    }
    if (in2) {
        __syncthreads();
        for (int idx = tid; idx < 64 * K2p; idx += 384) {
            int k = idx / 64, e = idx - (k * 64);
            int row = base + e;
            sT[k*64 + e] = (k < K2 && row < nrows) ? in2[(size_t)row * K2 + k] : 0.0f;
        }
        __syncthreads();
        for (int k = 0; k < K2p; k++) {
            float4 w = *(const float4*)&Ws2[k*96 + f0];
            #pragma unroll
            for (int i = 0; i < 4; i++) {
                float tv = sT[k*64 + r0 + i];
                acc[i][0] += tv * w.x; acc[i][1] += tv * w.y;
                acc[i][2] += tv * w.z; acc[i][3] += tv * w.w;
            }
        }
    }
    #pragma unroll
    for (int i = 0; i < 4; i++) {
        int row = base + r0 + i;
        if (row >= nrows) continue;
        float4 v;
        v.x = acc[i][0] + bias[f0+0];
        v.y = acc[i][1] + bias[f0+1];
        v.z = acc[i][2] + bias[f0+2];
        v.w = acc[i][3] + bias[f0+3];
        if (do_silu) {
            v.x = silu_f(v.x); v.y = silu_f(v.y);
            v.z = silu_f(v.z); v.w = silu_f(v.w);
        }
        *(float4*)&out[(size_t)row*96 + f0] = v;
    }
}

// ---------------- zero / pooling / readout ----------------------------------
__global__ void zero_aggr_kernel() {
    int i = blockIdx.x * 1024 + threadIdx.x;
    if (i < N_NODES * HDIM) g_aggr[i] = 0.0f;
}
__global__ void zero_pooled_kernel() {
    int i = blockIdx.x * 256 + threadIdx.x;
    if (i < N_GRAPHS * HDIM) g_pooled[i] = 0.0f;
}
__global__ void pool_kernel(const float* __restrict__ h2, const int* __restrict__ braw) {
    __shared__ int s_is64;
    if (threadIdx.x == 0) {
        s_is64 = ((braw[N_NODES-1] | braw[N_NODES-3] |
                   braw[N_NODES-5] | braw[N_NODES-7]) == 0) ? 1 : 0;
    }
    __syncthreads();
    int idx = blockIdx.x * blockDim.x + threadIdx.x;
    if (idx >= N_NODES * 24) return;
    int n = idx / 24, j = idx - n * 24;
    int g = s_is64 ? (int)((const long long*)braw)[n] : braw[n];
    float4 v = *(const float4*)&h2[(size_t)n*96 + j*4];
    red_add_v4(&g_pooled[g*96 + j*4], v);
}
__global__ void readout_kernel(const float* __restrict__ w1, const float* __restrict__ b1,
                               const float* __restrict__ w2, const float* __restrict__ b2,
                               float* __restrict__ out)
{
    __shared__ float p_s[96];
    __shared__ float t_s[96];
    int g = blockIdx.x, f = threadIdx.x;
    p_s[f] = g_pooled[g*96 + f];
    __syncthreads();
    float a = b1[f];
    #pragma unroll 8
    for (int k = 0; k < 96; k++) a += p_s[k] * w1[k*96 + f];
    t_s[f] = silu_f(a) * w2[f];
    __syncthreads();
    if (f < 32) {
        float sum = t_s[f] + t_s[f+32] + t_s[f+64];
        #pragma unroll
        for (int o = 16; o > 0; o >>= 1) sum += __shfl_down_sync(0xffffffffu, sum, o);
        if (f == 0) out[g] = sum + b2[0];
    }
}

// ---------------- host launcher ----------------------------------------------
extern "C" void kernel_launch(void* const* d_in, const int* in_sizes, int n_in,
                              void* d_out, int out_size)
{
    const float* x    = (const float*)d_in[0];
    const float* pos  = (const float*)d_in[1];
    const float* pe   = (const float*)d_in[2];
    const int*   eraw = (const int*)d_in[3];
    const int*   braw = (const int*)d_in[4];
    const float* ew1  = (const float*)d_in[5];
    const float* eb1  = (const float*)d_in[6];
    const float* ew2  = (const float*)d_in[7];
    const float* eb2  = (const float*)d_in[8];
    const float* mw1  = (const float*)d_in[9];
    const float* mb1  = (const float*)d_in[10];
    const float* mw2  = (const float*)d_in[11];
    const float* mb2  = (const float*)d_in[12];
    const float* uw1  = (const float*)d_in[13];
    const float* ub1  = (const float*)d_in[14];
    const float* uw2  = (const float*)d_in[15];
    const float* ub2  = (const float*)d_in[16];
    const float* pw1  = (const float*)d_in[17];
    const float* pb1  = (const float*)d_in[18];
    const float* pw2  = (const float*)d_in[19];
    const float* pb2  = (const float*)d_in[20];
    const float* rw1  = (const float*)d_in[21];
    const float* rb1  = (const float*)d_in[22];
    const float* rw2  = (const float*)d_in[23];
    const float* rb2  = (const float*)d_in[24];
    float* out = (float*)d_out;

    float *h_, *A_, *B_, *aggr_, *u_;
    uint32_t *Wp_, *Wplo_;
    cudaGetSymbolAddress((void**)&h_,    g_h);
    cudaGetSymbolAddress((void**)&A_,    g_A);
    cudaGetSymbolAddress((void**)&B_,    g_B);
    cudaGetSymbolAddress((void**)&aggr_, g_aggr);
    cudaGetSymbolAddress((void**)&u_,    g_u);
    cudaGetSymbolAddress((void**)&Wp_,   g_Wp);
    cudaGetSymbolAddress((void**)&Wplo_, g_Wplo);

    cudaFuncSetAttribute((const void*)node_mlp,
                         cudaFuncAttributeMaxDynamicSharedMemorySize, 32768);
    cudaFuncSetAttribute((const void*)mma_node,
                         cudaFuncAttributeMaxDynamicSharedMemorySize, 94208);
    cudaFuncSetAttribute((const void*)mma_edge,
                         cudaFuncAttributeMaxDynamicSharedMemorySize, 94208);

    const size_t smN = 22016u * 4u;            // 88064
    const size_t smE = (22016u + 672u) * 4u;   // 90752
    const int    nblk = (N_NODES + 127) / 128; // 391
    const int    eblk = 296;                   // persistent: 2 CTAs/SM x 148

    // edge prep + counting sort by rec
    zero_cnt_kernel<<<(N_NODES + 1023) / 1024, 1024>>>();
    edge_prep<<<(N_EDGES + 255) / 256, 256>>>(eraw, pos);
    scan_kernel<<<1, 1024>>>();
    scatter_kernel<<<(N_EDGES + 255) / 256, 256>>>();

    transpose_all<<<243, 1024>>>(mw1, mw2, uw1, uw2, ew2, pw1, pw2);
    pack_weights<<<122, 1024>>>();

    // embed layer 1 (scalar, K=11+24): u = silu([x,pe]@W1 + b1)
    {
        int K1p = 12, K2p = 24;
        size_t smem = (size_t)(K1p + K2p) * 96 * 4 + (size_t)64 * 24 * 4;
        dim3 tb(24, 16);
        node_mlp<<<(N_NODES + 63) / 64, tb, smem>>>(
            x, NUM_IN, ew1, pe, PE_DIM, ew1 + NUM_IN * 96, eb1, u_, N_NODES, 1);
    }
    // embed layer 2: h = u @ W2 + b2
    mma_node<<<nblk, 256, smN>>>(u_, nullptr, Wp_ + 110592, Wplo_ + 110592, 1,
                                 eb2, nullptr, h_, N_NODES, 0);

    for (int l = 0; l < N_LAYERS; l++) {
        size_t off = (size_t)l * 27648;
        const float* mb1l = mb1 + l * 96;
        const float* mb2l = mb2 + l * 96;
        const float* ub1l = ub1 + l * 96;
        const float* ub2l = ub2 + l * 96;
        const float* wll  = mw1 + (size_t)l * 193 * 96 + 192 * 96;  // dist row

        mma_node<<<nblk, 256, smN>>>(h_, nullptr, Wp_ + off, Wplo_ + off, 1,
                                     nullptr, nullptr, A_, N_NODES, 0);
        mma_node<<<nblk, 256, smN>>>(h_, nullptr, Wp_ + off + 4608, Wplo_ + off + 4608, 1,
                                     nullptr, nullptr, B_, N_NODES, 0);

        zero_aggr_kernel<<<(N_NODES * HDIM + 1023) / 1024, 1024>>>();
        mma_edge<<<eblk, 256, smE>>>(Wp_ + off + 9216, Wplo_ + off + 9216,
                                     wll, mb1l, mb2l);

        mma_node<<<nblk, 256, smN>>>(h_, aggr_, Wp_ + off + 13824, Wplo_ + off + 13824, 2,
                                     ub1l, nullptr, u_, N_NODES, 1);
        mma_node<<<nblk, 256, smN>>>(u_, nullptr, Wp_ + off + 23040, Wplo_ + off + 23040, 1,
                                     ub2l, h_, h_, N_NODES, 0);
    }

    // pre-MLP -> h2 (stored in g_A)
    mma_node<<<nblk, 256, smN>>>(h_, nullptr, Wp_ + 115200, Wplo_ + 115200, 1,
                                 pb1, nullptr, u_, N_NODES, 1);
    mma_node<<<nblk, 256, smN>>>(u_, nullptr, Wp_ + 119808, Wplo_ + 119808, 1,
                                 pb2, nullptr, A_, N_NODES, 0);

    zero_pooled_kernel<<<(N_GRAPHS * HDIM + 255) / 256, 256>>>();
    pool_kernel<<<(N_NODES * 24 + 255) / 256, 256>>>(A_, braw);
    readout_kernel<<<N_GRAPHS, 96>>>(rw1, rb1, rw2, rb2, out);
}

// round 17
// speedup vs baseline: 1.0703x; 1.0703x over previous
#include <cuda_runtime.h>
#include <cstdint>
#include <math.h>

#define N_NODES   50000
#define N_EDGES   800000
#define HDIM      96
#define NUM_IN    11
#define PE_DIM    24
#define N_LAYERS  4
#define N_GRAPHS  256

// ---------------- scratch (device globals; no allocations allowed) ----------
__device__ float g_h   [N_NODES * HDIM];
__device__ float g_A   [N_NODES * HDIM];
__device__ float g_B   [N_NODES * HDIM];
__device__ float g_aggr[N_NODES * HDIM];
__device__ float g_u   [N_NODES * HDIM];
__device__ float g_dist[N_EDGES];
__device__ int   g_send[N_EDGES];
__device__ int   g_rec [N_EDGES];
// sorted-by-rec copies
__device__ float g_sdist[N_EDGES];
__device__ int   g_ssend[N_EDGES];
__device__ int   g_srec [N_EDGES];
__device__ int   g_cnt  [N_NODES];
__device__ float g_pooled[N_GRAPHS * HDIM];
__device__ int   g_gcnt [N_GRAPHS];
// fp32 transposed weights WT[n][k] (staging for packing)
__device__ float g_WT[248832];
// packed bf16-pair weights (hi, lo): per 96-block of K: 48 words, layout
// word[(j%4)*12 + j/4] = bf16x2(k=2j, k=2j+1)
__device__ uint32_t g_Wp  [124416];
__device__ uint32_t g_Wplo[124416];

__device__ __forceinline__ float silu_f(float v) {
    return v / (1.0f + __expf(-v));
}
__device__ __forceinline__ void red_add_v4(float* p, float4 v) {
    asm volatile("red.global.add.v4.f32 [%0], {%1,%2,%3,%4};"
                 :: "l"(p), "f"(v.x), "f"(v.y), "f"(v.z), "f"(v.w) : "memory");
}
__device__ __forceinline__ uint32_t pkbf2(float x, float y) {
    uint32_t r;
    asm("cvt.rn.bf16x2.f32 %0, %1, %2;" : "=r"(r) : "f"(y), "f"(x));
    return r;
}
__device__ __forceinline__ float2 upbf2(uint32_t w) {
    float2 f;
    f.x = __uint_as_float(w << 16);
    f.y = __uint_as_float(w & 0xffff0000u);
    return f;
}
__device__ __forceinline__ void bfsplit2(float x, float y, uint32_t& h, uint32_t& l) {
    h = pkbf2(x, y);
    float2 r = upbf2(h);
    l = pkbf2(x - r.x, y - r.y);
}
__device__ __forceinline__ void mma16(float* d, uint32_t a0, uint32_t a1,
                                      uint32_t a2, uint32_t a3,
                                      uint32_t b0, uint32_t b1) {
    asm volatile(
        "mma.sync.aligned.m16n8k16.row.col.f32.bf16.bf16.f32 "
        "{%0,%1,%2,%3}, {%4,%5,%6,%7}, {%8,%9}, {%0,%1,%2,%3};"
        : "+f"(d[0]), "+f"(d[1]), "+f"(d[2]), "+f"(d[3])
        : "r"(a0), "r"(a1), "r"(a2), "r"(a3), "r"(b0), "r"(b1));
}

// SMEM word offsets: rows of 48 uint32 (pair-permuted), conflict-free LDS.128
#define AHI_W 0        // 128*48 = 6144
#define ALO_W 6144
#define BHI_W 12288    // 96*48 = 4608
#define BLO_W 16896
#define XTR_W 21504    // edge extras

// ---------------- edge preprocessing + histogram, dtype-robust --------------
__global__ void zero_cnt_kernel() {
    int i = blockIdx.x * 1024 + threadIdx.x;
    if (i < N_NODES) g_cnt[i] = 0;
}
__global__ void edge_prep(const int* __restrict__ eraw, const float* __restrict__ pos) {
    __shared__ int s_is64;
    if (threadIdx.x == 0) {
        s_is64 = ((eraw[2*N_EDGES-1] | eraw[2*N_EDGES-3] |
                   eraw[2*N_EDGES-5] | eraw[2*N_EDGES-7]) == 0) ? 1 : 0;
    }
    __syncthreads();
    int e = blockIdx.x * blockDim.x + threadIdx.x;
    if (e >= N_EDGES) return;
    int s, r;
    if (s_is64) {
        const long long* e64 = (const long long*)eraw;
        s = (int)e64[e]; r = (int)e64[N_EDGES + e];
    } else {
        s = eraw[e];     r = eraw[N_EDGES + e];
    }
    g_send[e] = s; g_rec[e] = r;
    float dx = pos[3*s+0] - pos[3*r+0];
    float dy = pos[3*s+1] - pos[3*r+1];
    float dz = pos[3*s+2] - pos[3*r+2];
    g_dist[e] = sqrtf(dx*dx + dy*dy + dz*dz);
    atomicAdd(&g_cnt[r], 1);
}
// 1-block exclusive prefix sum over g_cnt (becomes scatter cursor)
__global__ void __launch_bounds__(1024)
scan_kernel() {
    __shared__ int ssum[1024];
    int t = threadIdx.x;
    int beg = t * 49;
    int end = beg + 49; if (end > N_NODES) end = N_NODES;
    int s = 0;
    for (int i = beg; i < end; i++) s += g_cnt[i];
    ssum[t] = s;
    __syncthreads();
    for (int d = 1; d < 1024; d <<= 1) {
        int v = (t >= d) ? ssum[t - d] : 0;
        __syncthreads();
        ssum[t] += v;
        __syncthreads();
    }
    int off = (t > 0) ? ssum[t - 1] : 0;
    for (int i = beg; i < end; i++) {
        int c = g_cnt[i];
        g_cnt[i] = off;
        off += c;
    }
}
__global__ void scatter_kernel() {
    int e = blockIdx.x * blockDim.x + threadIdx.x;
    if (e >= N_EDGES) return;
    int r = g_rec[e];
    int pos = atomicAdd(&g_cnt[r], 1);
    g_ssend[pos] = g_send[e];
    g_srec [pos] = r;
    g_sdist[pos] = g_dist[e];
}

// ---------------- weight transpose (fp32 staging) ---------------------------
__global__ void __launch_bounds__(1024)
transpose_all(const float* __restrict__ mw1, const float* __restrict__ mw2,
              const float* __restrict__ uw1, const float* __restrict__ uw2,
              const float* __restrict__ ew2, const float* __restrict__ pw1,
              const float* __restrict__ pw2)
{
    __shared__ float t[32][33];
    int bid = blockIdx.x;
    const float* src; float* dst; int K; int tile;
    if (bid < 216) {
        int l = bid / 54, sub = bid % 54;
        float* WTl = g_WT + l * 55296;
        if (sub < 9)       { src = mw1 + (size_t)l*193*96;        dst = WTl;         K = 96;  tile = sub; }
        else if (sub < 18) { src = mw1 + (size_t)l*193*96 + 9216; dst = WTl + 9216;  K = 96;  tile = sub - 9; }
        else if (sub < 27) { src = mw2 + (size_t)l*9216;          dst = WTl + 18432; K = 96;  tile = sub - 18; }
        else if (sub < 45) { src = uw1 + (size_t)l*18432;         dst = WTl + 27648; K = 192; tile = sub - 27; }
        else               { src = uw2 + (size_t)l*9216;          dst = WTl + 46080; K = 96;  tile = sub - 45; }
    } else if (bid < 225) { src = ew2; dst = g_WT + 221184; K = 96; tile = bid - 216; }
    else if (bid < 234)   { src = pw1; dst = g_WT + 230400; K = 96; tile = bid - 225; }
    else                  { src = pw2; dst = g_WT + 239616; K = 96; tile = bid - 234; }
    int bx = tile % 3, by = tile / 3;
    int tx = threadIdx.x & 31, ty = threadIdx.x >> 5;
    t[ty][tx] = src[(by*32 + ty) * 96 + bx*32 + tx];
    __syncthreads();
    dst[(bx*32 + ty) * K + by*32 + tx] = t[tx][ty];
}

// pack fp32 WT into bf16-pair hi/lo in the SMEM-ready permuted layout
__global__ void __launch_bounds__(1024)
pack_weights() {
    int w = blockIdx.x * 1024 + threadIdx.x;
    if (w >= 124416) return;
    int b = w / 48, o = w - b * 48;
    int q = o % 12, tcp = o / 12;
    int j = 4 * q + tcp;
    int f = b * 96 + 2 * j;
    float x = g_WT[f], y = g_WT[f + 1];
    uint32_t h, l;
    bfsplit2(x, y, h, l);
    g_Wp[w] = h; g_Wplo[w] = l;
}

// ---- shared 3xBF16 mainloop: 8 warps (2m x 4n), warp tile 64 rows x 24 cols
__device__ __forceinline__ void mma3_loop(const uint32_t* apH, const uint32_t* apL,
                                          const uint32_t* bpH, const uint32_t* bpL,
                                          float acc[4][3][4])
{
    #pragma unroll
    for (int g = 0; g < 3; g++) {
        uint4 bh[3], bl[3];
        #pragma unroll
        for (int nf = 0; nf < 3; nf++) {
            bh[nf] = *(const uint4*)(bpH + nf * 384 + 4 * g);
            bl[nf] = *(const uint4*)(bpL + nf * 384 + 4 * g);
        }
        #pragma unroll
        for (int mf = 0; mf < 4; mf++) {
            uint4 xh = *(const uint4*)(apH + mf * 768 + 4 * g);
            uint4 yh = *(const uint4*)(apH + mf * 768 + 384 + 4 * g);
            uint4 xl = *(const uint4*)(apL + mf * 768 + 4 * g);
            uint4 yl = *(const uint4*)(apL + mf * 768 + 384 + 4 * g);
            #pragma unroll
            for (int nf = 0; nf < 3; nf++) {
                mma16(acc[mf][nf], xh.x, yh.x, xh.y, yh.y, bh[nf].x, bh[nf].y);
                mma16(acc[mf][nf], xh.x, yh.x, xh.y, yh.y, bl[nf].x, bl[nf].y);
                mma16(acc[mf][nf], xl.x, yl.x, xl.y, yl.y, bh[nf].x, bh[nf].y);
                mma16(acc[mf][nf], xh.z, yh.z, xh.w, yh.w, bh[nf].z, bh[nf].w);
                mma16(acc[mf][nf], xh.z, yh.z, xh.w, yh.w, bl[nf].z, bl[nf].w);
                mma16(acc[mf][nf], xl.z, yl.z, xl.w, yl.w, bh[nf].z, bh[nf].w);
            }
        }
    }
}

// store A pair (float4 covering k=4*k4..4*k4+3) as hi/lo packed words
__device__ __forceinline__ void store_apair(uint32_t* Ah, uint32_t* Al,
                                            int row, int k4, float4 v)
{
    uint32_t h0, l0, h1, l1;
    bfsplit2(v.x, v.y, h0, l0);
    bfsplit2(v.z, v.w, h1, l1);
    int j0 = 2 * k4, j1 = 2 * k4 + 1;
    int o0 = (j0 & 3) * 12 + (j0 >> 2);
    int o1 = (j1 & 3) * 12 + (j1 >> 2);
    Ah[row * 48 + o0] = h0; Ah[row * 48 + o1] = h1;
    Al[row * 48 + o0] = l0; Al[row * 48 + o1] = l1;
}

// ---------------- mma node MLP: out = act([in1|in2] @ W + b)[+res] ----------
// 256 thr = 8 warps (2 m x 4 n), CTA tile 128 rows x 96 cols, K in 96-chunks
// zaggr: also zero g_aggr rows for this tile (fuses the zeroing launch)
__global__ void __launch_bounds__(256, 2)
mma_node(const float* __restrict__ in1, const float* __restrict__ in2,
         const uint32_t* __restrict__ Wp, const uint32_t* __restrict__ Wplo, int Kc,
         const float* __restrict__ bias, const float* __restrict__ res,
         float* __restrict__ out, int nrows, int do_silu, int zaggr)
{
    extern __shared__ uint32_t smw[];
    uint32_t* Ah = smw + AHI_W;
    uint32_t* Al = smw + ALO_W;
    uint32_t* Bh = smw + BHI_W;
    uint32_t* Bl = smw + BLO_W;
    float*    Cs = (float*)smw;

    const int tid = threadIdx.x;
    const int w   = tid >> 5, lane = tid & 31;
    const int wm  = w & 1, wn = w >> 1;
    const int tr  = lane >> 2, tc = lane & 3;
    const int base = blockIdx.x * 128;

    float acc[4][3][4];
    #pragma unroll
    for (int mf = 0; mf < 4; mf++)
        #pragma unroll
        for (int nf = 0; nf < 3; nf++)
            #pragma unroll
            for (int c = 0; c < 4; c++) acc[mf][nf][c] = 0.0f;

    for (int ch = 0; ch < Kc; ch++) {
        const float* src = (ch == 0) ? in1 : in2;
        #pragma unroll
        for (int it = 0; it < 12; it++) {
            int idx = it * 256 + tid;
            int row = idx / 24, k4 = idx - row * 24;
            int grow = base + row;
            float4 v = make_float4(0.f, 0.f, 0.f, 0.f);
            if (grow < nrows) v = *(const float4*)&src[(size_t)grow * 96 + k4 * 4];
            store_apair(Ah, Al, row, k4, v);
        }
        #pragma unroll
        for (int it = 0; it < 5; it++) {
            int idx = it * 256 + tid;
            if (idx < 1152) {
                int n = idx / 12, o4 = idx - n * 12;
                const uint4* sh = (const uint4*)(Wp   + ((size_t)n * Kc + ch) * 48) + o4;
                const uint4* sl = (const uint4*)(Wplo + ((size_t)n * Kc + ch) * 48) + o4;
                ((uint4*)(Bh + n * 48))[o4] = *sh;
                ((uint4*)(Bl + n * 48))[o4] = *sl;
            }
        }
        __syncthreads();

        const uint32_t* apH = Ah + (wm * 64 + tr) * 48 + tc * 12;
        const uint32_t* apL = Al + (wm * 64 + tr) * 48 + tc * 12;
        const uint32_t* bpH = Bh + (wn * 24 + tr) * 48 + tc * 12;
        const uint32_t* bpL = Bl + (wn * 24 + tr) * 48 + tc * 12;
        mma3_loop(apH, apL, bpH, bpL, acc);
        __syncthreads();
    }

    #pragma unroll
    for (int mf = 0; mf < 4; mf++) {
        int row = wm * 64 + mf * 16 + tr;
        int col = wn * 24 + 2 * tc;
        #pragma unroll
        for (int nf = 0; nf < 3; nf++) {
            Cs[row * 100 + col + nf*8]       = acc[mf][nf][0];
            Cs[row * 100 + col + nf*8 + 1]   = acc[mf][nf][1];
            Cs[(row+8) * 100 + col + nf*8]   = acc[mf][nf][2];
            Cs[(row+8) * 100 + col + nf*8+1] = acc[mf][nf][3];
        }
    }
    __syncthreads();

    #pragma unroll
    for (int it = 0; it < 12; it++) {
        int idx = it * 256 + tid;
        int row = idx / 24, j4 = idx - row * 24;
        int grow = base + row;
        if (grow >= nrows) continue;
        float4 v = *(const float4*)&Cs[row * 100 + j4 * 4];
        if (bias) {
            float4 b = *(const float4*)&bias[j4 * 4];
            v.x += b.x; v.y += b.y; v.z += b.z; v.w += b.w;
        }
        if (do_silu) {
            v.x = silu_f(v.x); v.y = silu_f(v.y);
            v.z = silu_f(v.z); v.w = silu_f(v.w);
        }
        if (res) {
            float4 rv = *(const float4*)&res[(size_t)grow * 96 + j4 * 4];
            v.x += rv.x; v.y += rv.y; v.z += rv.z; v.w += rv.w;
        }
        *(float4*)&out[(size_t)grow * 96 + j4 * 4] = v;
        if (zaggr)
            *(float4*)&g_aggr[(size_t)grow * 96 + j4 * 4] =
                make_float4(0.f, 0.f, 0.f, 0.f);
    }
}

// ---------------- mma fused edge message + segmented-scan aggregation -------
// edges sorted by rec: t = silu(A[s]+B[r]+d*wl+b1); m = silu(t@W2+b2);
// epilogue: warp-local segmented scan over 32-row groups, tail lanes red.add
__global__ void __launch_bounds__(256, 2)
mma_edge(const uint32_t* __restrict__ Wp, const uint32_t* __restrict__ Wplo,
         const float* __restrict__ wl, const float* __restrict__ b1,
         const float* __restrict__ b2)
{
    extern __shared__ uint32_t smw[];
    uint32_t* Ah = smw + AHI_W;
    uint32_t* Al = smw + ALO_W;
    uint32_t* Bh = smw + BHI_W;
    uint32_t* Bl = smw + BLO_W;
    float*    Cs = (float*)smw;
    float* b1s = (float*)(smw + XTR_W);
    float* b2s = b1s + 96;
    float* wls = b2s + 96;
    float* de  = wls + 96;
    int*   se  = (int*)(de + 128);
    int*   re  = se + 128;

    const int tid = threadIdx.x;
    const int w   = tid >> 5, lane = tid & 31;
    const int wm  = w & 1, wn = w >> 1;
    const int tr  = lane >> 2, tc = lane & 3;
    const int base = blockIdx.x * 128;

    if (tid < 96) { b1s[tid] = b1[tid]; b2s[tid] = b2[tid]; wls[tid] = wl[tid]; }
    else if (tid >= 128) {
        int j = tid - 128; int e = base + j;
        se[j] = g_ssend[e]; re[j] = g_srec[e]; de[j] = g_sdist[e];
    }
    #pragma unroll
    for (int it = 0; it < 5; it++) {
        int idx = it * 256 + tid;
        if (idx < 1152) {
            int n = idx / 12, o4 = idx - n * 12;
            ((uint4*)(Bh + n * 48))[o4] = ((const uint4*)(Wp   + (size_t)n * 48))[o4];
            ((uint4*)(Bl + n * 48))[o4] = ((const uint4*)(Wplo + (size_t)n * 48))[o4];
        }
    }
    __syncthreads();

    #pragma unroll
    for (int it = 0; it < 12; it++) {
        int idx = it * 256 + tid;
        int e = idx / 24, k4 = idx - e * 24;
        int kf = k4 * 4;
        int s = se[e], r = re[e];
        float dd = de[e];
        float4 a  = *(const float4*)&g_A[(size_t)s * 96 + kf];
        float4 b  = *(const float4*)&g_B[(size_t)r * 96 + kf];
        float4 w4 = *(const float4*)&wls[kf];
        float4 c4 = *(const float4*)&b1s[kf];
        float4 t;
        t.x = silu_f(a.x + b.x + dd * w4.x + c4.x);
        t.y = silu_f(a.y + b.y + dd * w4.y + c4.y);
        t.z = silu_f(a.z + b.z + dd * w4.z + c4.z);
        t.w = silu_f(a.w + b.w + dd * w4.w + c4.w);
        store_apair(Ah, Al, e, k4, t);
    }
    __syncthreads();

    float acc[4][3][4];
    #pragma unroll
    for (int mf = 0; mf < 4; mf++)
        #pragma unroll
        for (int nf = 0; nf < 3; nf++)
            #pragma unroll
            for (int c = 0; c < 4; c++) acc[mf][nf][c] = 0.0f;

    const uint32_t* apH = Ah + (wm * 64 + tr) * 48 + tc * 12;
    const uint32_t* apL = Al + (wm * 64 + tr) * 48 + tc * 12;
    const uint32_t* bpH = Bh + (wn * 24 + tr) * 48 + tc * 12;
    const uint32_t* bpL = Bl + (wn * 24 + tr) * 48 + tc * 12;
    mma3_loop(apH, apL, bpH, bpL, acc);
    __syncthreads();

    #pragma unroll
    for (int mf = 0; mf < 4; mf++) {
        int row = wm * 64 + mf * 16 + tr;
        int col = wn * 24 + 2 * tc;
        #pragma unroll
        for (int nf = 0; nf < 3; nf++) {
            Cs[row * 100 + col + nf*8]       = acc[mf][nf][0];
            Cs[row * 100 + col + nf*8 + 1]   = acc[mf][nf][1];
            Cs[(row+8) * 100 + col + nf*8]   = acc[mf][nf][2];
            Cs[(row+8) * 100 + col + nf*8+1] = acc[mf][nf][3];
        }
    }
    __syncthreads();

    // segmented-scan epilogue: 96 warp-tasks = (group 0..3) x (j4 0..23)
    for (int t = w; t < 96; t += 8) {
        int grp = t & 3, j4 = t >> 2;
        int row = grp * 32 + lane;
        int node = re[row];
        float4 b = *(const float4*)&b2s[j4 * 4];
        float4 v = *(const float4*)&Cs[row * 100 + j4 * 4];
        v.x = silu_f(v.x + b.x); v.y = silu_f(v.y + b.y);
        v.z = silu_f(v.z + b.z); v.w = silu_f(v.w + b.w);
        #pragma unroll
        for (int d = 1; d < 32; d <<= 1) {
            float ox = __shfl_up_sync(0xffffffffu, v.x, d);
            float oy = __shfl_up_sync(0xffffffffu, v.y, d);
            float oz = __shfl_up_sync(0xffffffffu, v.z, d);
            float ow = __shfl_up_sync(0xffffffffu, v.w, d);
            int   on = __shfl_up_sync(0xffffffffu, node, d);
            if (lane >= d && on == node) {
                v.x += ox; v.y += oy; v.z += oz; v.w += ow;
            }
        }
        int nn = __shfl_down_sync(0xffffffffu, node, 1);
        bool tail = (lane == 31) || (nn != node);
        if (tail) red_add_v4(&g_aggr[(size_t)node * 96 + j4 * 4], v);
    }
}

// ---------------- scalar node MLP (embed layer 1 only, K=11+24) -------------
__global__ void __launch_bounds__(384, 2)
node_mlp(const float* __restrict__ in1, int K1, const float* __restrict__ W1,
         const float* __restrict__ in2, int K2, const float* __restrict__ W2,
         const float* __restrict__ bias, float* __restrict__ out,
         int nrows, int do_silu)
{
    extern __shared__ float smf[];
    const int K1p = (K1 + 3) & ~3;
    const int K2p = (K2 + 3) & ~3;
    float* Ws1 = smf;
    float* Ws2 = smf + K1p * 96;
    float* sT  = Ws2 + K2p * 96;

    const int tid  = threadIdx.y * 24 + threadIdx.x;
    const int base = blockIdx.x * 64;
    const int f0   = threadIdx.x * 4;
    const int r0   = threadIdx.y * 4;

    for (int idx = tid; idx < K1p * 96; idx += 384) {
        int k = idx / 96;
        Ws1[idx] = (k < K1) ? W1[idx] : 0.0f;
    }
    if (in2) {
        for (int idx = tid; idx < K2p * 96; idx += 384) {
            int k = idx / 96;
            Ws2[idx] = (k < K2) ? W2[idx] : 0.0f;
        }
    }

    float acc[4][4];
    #pragma unroll
    for (int i = 0; i < 4; i++)
        #pragma unroll
        for (int c = 0; c < 4; c++) acc[i][c] = 0.0f;

    for (int idx = tid; idx < 64 * K1p; idx += 384) {
        int k = idx / 64, e = idx - (k * 64);
        int row = base + e;
        sT[k*64 + e] = (k < K1 && row < nrows) ? in1[(size_t)row * K1 + k] : 0.0f;
    }
    __syncthreads();
    for (int k = 0; k < K1p; k++) {
        float4 w = *(const float4*)&Ws1[k*96 + f0];
        #pragma unroll
        for (int i = 0; i < 4; i++) {
            float tv = sT[k*64 + r0 + i];
            acc[i][0] += tv * w.x; acc[i][1] += tv * w.y;
            acc[i][2] += tv * w.z; acc[i][3] += tv * w.w;
        }
    }
    if (in2) {
        __syncthreads();
        for (int idx = tid; idx < 64 * K2p; idx += 384) {
            int k = idx / 64, e = idx - (k * 64);
            int row = base + e;
            sT[k*64 + e] = (k < K2 && row < nrows) ? in2[(size_t)row * K2 + k] : 0.0f;
        }
        __syncthreads();
        for (int k = 0; k < K2p; k++) {
            float4 w = *(const float4*)&Ws2[k*96 + f0];
            #pragma unroll
            for (int i = 0; i < 4; i++) {
                float tv = sT[k*64 + r0 + i];
                acc[i][0] += tv * w.x; acc[i][1] += tv * w.y;
                acc[i][2] += tv * w.z; acc[i][3] += tv * w.w;
            }
        }
    }
    #pragma unroll
    for (int i = 0; i < 4; i++) {
        int row = base + r0 + i;
        if (row >= nrows) continue;
        float4 v;
        v.x = acc[i][0] + bias[f0+0];
        v.y = acc[i][1] + bias[f0+1];
        v.z = acc[i][2] + bias[f0+2];
        v.w = acc[i][3] + bias[f0+3];
        if (do_silu) {
            v.x = silu_f(v.x); v.y = silu_f(v.y);
            v.z = silu_f(v.z); v.w = silu_f(v.w);
        }
        *(float4*)&out[(size_t)row*96 + f0] = v;
    }
}

// ---------------- pooling / readout ------------------------------------------
__global__ void zero_pooled_kernel() {
    int i = blockIdx.x * 256 + threadIdx.x;
    if (i < N_GRAPHS * HDIM) g_pooled[i] = 0.0f;
    if (i < N_GRAPHS) g_gcnt[i] = 0;
}
// pools u = silu(h@P1+b1) and counts nodes per graph
__global__ void pool_kernel(const float* __restrict__ uin, const int* __restrict__ braw) {
    __shared__ int s_is64;
    if (threadIdx.x == 0) {
        s_is64 = ((braw[N_NODES-1] | braw[N_NODES-3] |
                   braw[N_NODES-5] | braw[N_NODES-7]) == 0) ? 1 : 0;
    }
    __syncthreads();
    int idx = blockIdx.x * blockDim.x + threadIdx.x;
    if (idx >= N_NODES * 24) return;
    int n = idx / 24, j = idx - n * 24;
    int g = s_is64 ? (int)((const long long*)braw)[n] : braw[n];
    float4 v = *(const float4*)&uin[(size_t)n*96 + j*4];
    red_add_v4(&g_pooled[g*96 + j*4], v);
    if (j == 0) atomicAdd(&g_gcnt[g], 1);
}
// p = pooled_u @ P2 + cnt*pb2;  out = silu(p@rw1+rb1)@rw2 + rb2
__global__ void readout_kernel(const float* __restrict__ pw2, const float* __restrict__ pb2,
                               const float* __restrict__ w1, const float* __restrict__ b1,
                               const float* __restrict__ w2, const float* __restrict__ b2,
                               float* __restrict__ out)
{
    __shared__ float pu_s[96];
    __shared__ float p_s[96];
    __shared__ float t_s[96];
    int g = blockIdx.x, f = threadIdx.x;
    pu_s[f] = g_pooled[g*96 + f];
    __syncthreads();
    float cnt = (float)g_gcnt[g];
    float p = cnt * pb2[f];
    #pragma unroll 8
    for (int k = 0; k < 96; k++) p += pu_s[k] * pw2[k*96 + f];
    p_s[f] = p;
    __syncthreads();
    float a = b1[f];
    #pragma unroll 8
    for (int k = 0; k < 96; k++) a += p_s[k] * w1[k*96 + f];
    t_s[f] = silu_f(a) * w2[f];
    __syncthreads();
    if (f < 32) {
        float sum = t_s[f] + t_s[f+32] + t_s[f+64];
        #pragma unroll
        for (int o = 16; o > 0; o >>= 1) sum += __shfl_down_sync(0xffffffffu, sum, o);
        if (f == 0) out[g] = sum + b2[0];
    }
}

// ---------------- host launcher ----------------------------------------------
extern "C" void kernel_launch(void* const* d_in, const int* in_sizes, int n_in,
                              void* d_out, int out_size)
{
    const float* x    = (const float*)d_in[0];
    const float* pos  = (const float*)d_in[1];
    const float* pe   = (const float*)d_in[2];
    const int*   eraw = (const int*)d_in[3];
    const int*   braw = (const int*)d_in[4];
    const float* ew1  = (const float*)d_in[5];
    const float* eb1  = (const float*)d_in[6];
    const float* ew2  = (const float*)d_in[7];
    const float* eb2  = (const float*)d_in[8];
    const float* mw1  = (const float*)d_in[9];
    const float* mb1  = (const float*)d_in[10];
    const float* mw2  = (const float*)d_in[11];
    const float* mb2  = (const float*)d_in[12];
    const float* uw1  = (const float*)d_in[13];
    const float* ub1  = (const float*)d_in[14];
    const float* uw2  = (const float*)d_in[15];
    const float* ub2  = (const float*)d_in[16];
    const float* pw1  = (const float*)d_in[17];
    const float* pb1  = (const float*)d_in[18];
    const float* pw2  = (const float*)d_in[19];
    const float* pb2  = (const float*)d_in[20];
    const float* rw1  = (const float*)d_in[21];
    const float* rb1  = (const float*)d_in[22];
    const float* rw2  = (const float*)d_in[23];
    const float* rb2  = (const float*)d_in[24];
    float* out = (float*)d_out;

    float *h_, *A_, *B_, *aggr_, *u_;
    uint32_t *Wp_, *Wplo_;
    cudaGetSymbolAddress((void**)&h_,    g_h);
    cudaGetSymbolAddress((void**)&A_,    g_A);
    cudaGetSymbolAddress((void**)&B_,    g_B);
    cudaGetSymbolAddress((void**)&aggr_, g_aggr);
    cudaGetSymbolAddress((void**)&u_,    g_u);
    cudaGetSymbolAddress((void**)&Wp_,   g_Wp);
    cudaGetSymbolAddress((void**)&Wplo_, g_Wplo);

    cudaFuncSetAttribute((const void*)node_mlp,
                         cudaFuncAttributeMaxDynamicSharedMemorySize, 32768);
    cudaFuncSetAttribute((const void*)mma_node,
                         cudaFuncAttributeMaxDynamicSharedMemorySize, 90112);
    cudaFuncSetAttribute((const void*)mma_edge,
                         cudaFuncAttributeMaxDynamicSharedMemorySize, 90112);

    const size_t smN = 21504u * 4u;            // 86016
    const size_t smE = (21504u + 672u) * 4u;   // 88704
    const int    nblk = (N_NODES + 127) / 128; // 391

    // edge prep + counting sort by rec
    zero_cnt_kernel<<<(N_NODES + 1023) / 1024, 1024>>>();
    edge_prep<<<(N_EDGES + 255) / 256, 256>>>(eraw, pos);
    scan_kernel<<<1, 1024>>>();
    scatter_kernel<<<(N_EDGES + 255) / 256, 256>>>();

    transpose_all<<<243, 1024>>>(mw1, mw2, uw1, uw2, ew2, pw1, pw2);
    pack_weights<<<122, 1024>>>();

    // embed layer 1 (scalar, K=11+24): u = silu([x,pe]@W1 + b1)
    {
        int K1p = 12, K2p = 24;
        size_t smem = (size_t)(K1p + K2p) * 96 * 4 + (size_t)64 * 24 * 4;
        dim3 tb(24, 16);
        node_mlp<<<(N_NODES + 63) / 64, tb, smem>>>(
            x, NUM_IN, ew1, pe, PE_DIM, ew1 + NUM_IN * 96, eb1, u_, N_NODES, 1);
    }
    // embed layer 2: h = u @ W2 + b2
    mma_node<<<nblk, 256, smN>>>(u_, nullptr, Wp_ + 110592, Wplo_ + 110592, 1,
                                 eb2, nullptr, h_, N_NODES, 0, 0);

    for (int l = 0; l < N_LAYERS; l++) {
        size_t off = (size_t)l * 27648;
        const float* mb1l = mb1 + l * 96;
        const float* mb2l = mb2 + l * 96;
        const float* ub1l = ub1 + l * 96;
        const float* ub2l = ub2 + l * 96;
        const float* wll  = mw1 + (size_t)l * 193 * 96 + 192 * 96;  // dist row

        mma_node<<<nblk, 256, smN>>>(h_, nullptr, Wp_ + off, Wplo_ + off, 1,
                                     nullptr, nullptr, A_, N_NODES, 0, 0);
        // B-output launch also zeroes g_aggr rows (fused zeroing)
        mma_node<<<nblk, 256, smN>>>(h_, nullptr, Wp_ + off + 4608, Wplo_ + off + 4608, 1,
                                     nullptr, nullptr, B_, N_NODES, 0, 1);

        mma_edge<<<N_EDGES / 128, 256, smE>>>(Wp_ + off + 9216, Wplo_ + off + 9216,
                                              wll, mb1l, mb2l);

        mma_node<<<nblk, 256, smN>>>(h_, aggr_, Wp_ + off + 13824, Wplo_ + off + 13824, 2,
                                     ub1l, nullptr, u_, N_NODES, 1, 0);
        mma_node<<<nblk, 256, smN>>>(u_, nullptr, Wp_ + off + 23040, Wplo_ + off + 23040, 1,
                                     ub2l, h_, h_, N_NODES, 0, 0);
    }

    // pre-MLP layer 1: u = silu(h@P1 + pb1); P2 folded into readout via pooling
    mma_node<<<nblk, 256, smN>>>(h_, nullptr, Wp_ + 115200, Wplo_ + 115200, 1,
                                 pb1, nullptr, u_, N_NODES, 1, 0);

    zero_pooled_kernel<<<(N_GRAPHS * HDIM + 255) / 256, 256>>>();
    pool_kernel<<<(N_NODES * 24 + 255) / 256, 256>>>(u_, braw);
    readout_kernel<<<N_GRAPHS, 96>>>(pw2, pb2, rw1, rb1, rw2, rb2, out);
}